// round 9
// baseline (speedup 1.0000x reference)
#include <cuda_runtime.h>

#define BATCH  64
#define NTOK   577
#define PTOK   576      // patches
#define DENS   288      // kept dense tokens
#define SSZ    288      // skipped tokens
#define GSZ    144      // selected group size
#define DIM    768
#define OUTROWS 433     // 1 + DENS + GSZ
#define RCOLS  432      // DENS + GSZ
#define EMAX   1200     // <= 4*288 = 1152 edges max

// ---------------- scratch (device globals; no allocation) ----------------
__device__ int   g_order[BATCH][PTOK];          // argsort(-cls_attn)
__device__ int   g_t2[BATCH][SSZ][2];           // top-2 neighbor per skip row
__device__ int   g_rowmap[BATCH][OUTROWS];      // attention/tk row index per output row
__device__ int   g_colmap[BATCH][RCOLS];        // attention col index per R column
__device__ int   g_ein[BATCH][EMAX];            // tk row index of edge source (alive only)
__device__ float g_ew[BATCH][EMAX];             // edge weight (alive only)
__device__ int   g_selrange[BATCH][GSZ][2];     // compacted [start,end) per selected node

// ---------------- kernel A: argsort(-cls_attn), stable, 4 segs/batch -------
__global__ __launch_bounds__(192) void k_order(const float* __restrict__ attn) {
    const int b   = blockIdx.y;
    const int seg = blockIdx.x;                 // 0..3 -> elements seg*144..+143
    __shared__ float a[PTOK];
    for (int p = threadIdx.x; p < PTOK; p += 192)
        a[p] = attn[(size_t)b * NTOK * PTOK + p];
    __syncthreads();
    if (threadIdx.x < 144) {
        const int p = seg * 144 + threadIdx.x;
        const float v = a[p];
        int r = 0;
        const float4* a4 = (const float4*)a;
        #pragma unroll 4
        for (int q4 = 0; q4 < PTOK / 4; q4++) {
            float4 u4 = a4[q4];
            int qb = q4 * 4;
            r += (u4.x > v) || (u4.x == v && qb     < p);
            r += (u4.y > v) || (u4.y == v && qb + 1 < p);
            r += (u4.z > v) || (u4.z == v && qb + 2 < p);
            r += (u4.w > v) || (u4.w == v && qb + 3 < p);
        }
        g_order[b][r] = p;                      // ranks are unique -> disjoint
    }
}

// ---------------- kernel B: top-2 per skip row (1 warp per row) ------------
__global__ __launch_bounds__(256) void k_top2(const float* __restrict__ attn) {
    const int b    = blockIdx.y;
    const int warp = threadIdx.x >> 5;          // 8 warps
    const int lane = threadIdx.x & 31;
    const int i    = blockIdx.x * 8 + warp;     // skip row index 0..287

    __shared__ int   ords[SSZ];
    __shared__ float rows[8][PTOK];

    for (int j = threadIdx.x; j < SSZ; j += 256) ords[j] = g_order[b][DENS + j];
    __syncthreads();

    const int ri = 1 + ords[i];
    const float* src = attn + ((size_t)b * NTOK + ri) * PTOK;
    for (int p = lane; p < PTOK; p += 32) rows[warp][p] = src[p];
    __syncwarp();

    // local top-2 with key = (monotone(value), 287-j): tie -> smaller j wins
    unsigned long long k1 = 0ull, k2 = 0ull;
    #pragma unroll
    for (int k = 0; k < 9; k++) {
        int j = lane + k * 32;
        if (j == i) continue;
        float v = rows[warp][ords[j]];
        unsigned ub = __float_as_uint(v);
        ub ^= (unsigned)(((int)ub >> 31)) | 0x80000000u;   // total order on floats
        unsigned long long key = ((unsigned long long)ub << 32) | (unsigned)(SSZ - 1 - j);
        if (key > k1)      { k2 = k1; k1 = key; }
        else if (key > k2) { k2 = key; }
    }
    #pragma unroll
    for (int off = 16; off > 0; off >>= 1) {
        unsigned long long o1 = __shfl_down_sync(0xffffffffu, k1, off);
        unsigned long long o2 = __shfl_down_sync(0xffffffffu, k2, off);
        if (o1 > k1) { k2 = (k1 > o2) ? k1 : o2; k1 = o1; }
        else         { k2 = (k2 > o1) ? k2 : o1; }
    }
    if (lane == 0) {
        g_t2[b][i][0] = SSZ - 1 - (int)(k1 & 0xffffffffu);
        g_t2[b][i][1] = SSZ - 1 - (int)(k2 & 0xffffffffu);
    }
}

// ---- parallel exclusive scan over 288 per-thread values (288 threads) -----
__device__ __forceinline__ void scan288(int tid, int v, int* offs, int* wsum) {
    const int lane = tid & 31, warp = tid >> 5;     // 9 warps
    int incl = v;
    #pragma unroll
    for (int off = 1; off < 32; off <<= 1) {
        int n = __shfl_up_sync(0xffffffffu, incl, off);
        if (lane >= off) incl += n;
    }
    if (lane == 31) wsum[warp] = incl;
    __syncthreads();
    if (tid == 0) {
        int acc = 0;
        #pragma unroll
        for (int w = 0; w < 9; w++) { int t = wsum[w]; wsum[w] = acc; acc += t; }
        offs[SSZ] = acc;
    }
    __syncthreads();
    offs[tid] = incl - v + wsum[warp];
    __syncthreads();
}

// ---------------- kernel C: symmetrize + CSR + prune + select --------------
__global__ __launch_bounds__(288) void k_graph2(const float* __restrict__ attn) {
    const int b   = blockIdx.x;
    const int tid = threadIdx.x;                 // 288 threads
    const float* A0 = attn + (size_t)b * NTOK * PTOK;

    __shared__ int   order[PTOK];
    __shared__ unsigned colbits[SSZ * 9];        // bit i of colbits[j*9+(i>>5)] = edge i->j
    __shared__ int   offs[SSZ + 1];
    __shared__ int   coffs[SSZ + 1];
    __shared__ int   ein[EMAX];
    __shared__ float ew[EMAX];
    __shared__ unsigned char alive[EMAX];
    __shared__ float favg[2][SSZ];               // double-buffered averages
    __shared__ int   degi[SSZ];
    __shared__ int   gsel[GSZ];
    __shared__ int   wsum[9];

    for (int p = tid; p < PTOK; p += 288) order[p] = g_order[b][p];
    for (int k = tid; k < SSZ * 9; k += 288) colbits[k] = 0;
    __syncthreads();

    // symmetrize (column-major bit store)
    {
        const int i = tid;
        const int j1 = g_t2[b][i][0], j2 = g_t2[b][i][1];
        atomicOr(&colbits[j1 * 9 + (i >> 5)], 1u << (i & 31));   // i -> j1
        atomicOr(&colbits[j2 * 9 + (i >> 5)], 1u << (i & 31));   // i -> j2
        atomicOr(&colbits[i * 9 + (j1 >> 5)], 1u << (j1 & 31));  // j1 -> i
        atomicOr(&colbits[i * 9 + (j2 >> 5)], 1u << (j2 & 31));  // j2 -> i
    }
    __syncthreads();

    // per-column in-degree via popcount, then exclusive scan
    int mycnt = 0;
    #pragma unroll
    for (int w = 0; w < 9; w++) mycnt += __popc(colbits[tid * 9 + w]);
    scan288(tid, mycnt, offs, wsum);

    const int j   = tid;
    const int st0 = offs[j], en0 = offs[j + 1];

    // fill incoming CSR (i ascending within each j) via ffs walk. M = (W != 0)
    {
        const int cj = order[DENS + j];
        int ptr = st0;
        #pragma unroll
        for (int w = 0; w < 9; w++) {
            unsigned m = colbits[j * 9 + w];
            while (m) {
                int i = w * 32 + __ffs(m) - 1;
                m &= m - 1;
                float wv = A0[(size_t)(1 + order[DENS + i]) * PTOK + cj];
                ein[ptr] = i;
                ew[ptr]  = wv;
                alive[ptr] = (wv != 0.f) ? 1 : 0;
                ptr++;
            }
        }
    }

    // initial averages (own column only -> no barrier needed yet)
    int cur = 0;
    {
        int dg = 0; float s = 0.f;
        for (int e = st0; e < en0; e++)
            if (alive[e]) { dg++; s += ew[e]; }
        degi[j] = dg;
        favg[0][j] = (dg > 0) ? (s / (float)dg) : 0.f;
    }
    __syncthreads();                             // favg[0] visible to all

    // fixed point: ONE barrier-op per iteration
    for (;;) {
        const float aj = favg[cur][j];
        int ch = 0;
        for (int e = st0; e < en0; e++)
            if (alive[e] && !(aj > favg[cur][ein[e]])) { alive[e] = 0; ch = 1; }
        int dg = 0; float s = 0.f;
        for (int e = st0; e < en0; e++)
            if (alive[e]) { dg++; s += ew[e]; }
        degi[j] = dg;
        favg[cur ^ 1][j] = (dg > 0) ? (s / (float)dg) : 0.f;
        if (!__syncthreads_or(ch)) break;
        cur ^= 1;
    }
    // degi[j] == final alive in-degree

    // compacted offsets over final degrees
    scan288(tid, degi[tid], coffs, wsum);

    // top-144 by in-degree (ties -> smaller index first)
    {
        const int dj = degi[j];
        int r = 0;
        for (int q = 0; q < SSZ; q++) {
            int dq = degi[q];
            r += (dq > dj) || (dq == dj && q < j);
        }
        if (r < GSZ) gsel[r] = j;
    }

    // compacted alive edges to global (tk-row-resolved)
    {
        int ptr = coffs[j];
        for (int e = st0; e < en0; e++) {
            if (alive[e]) {
                g_ein[b][ptr] = 1 + order[DENS + ein[e]];
                g_ew[b][ptr]  = ew[e];
                ptr++;
            }
        }
    }
    __syncthreads();

    for (int g = tid; g < GSZ; g += 288) {
        int jj = gsel[g];
        g_selrange[b][g][0] = coffs[jj];
        g_selrange[b][g][1] = coffs[jj] + degi[jj];
    }
    for (int u = tid; u < OUTROWS; u += 288) {
        int row;
        if (u == 0)            row = 0;
        else if (u <= DENS)    row = 1 + order[u - 1];
        else                   row = 1 + order[DENS + gsel[u - 1 - DENS]];
        g_rowmap[b][u] = row;
    }
    for (int v = tid; v < RCOLS; v += 288) {
        int c;
        if (v < DENS) c = order[v];
        else          c = order[DENS + gsel[v - DENS]];
        g_colmap[b][v] = c;
    }
}

// -------- fused output kernel, 2 rows/block (heavy paired with light) ------
// block ub handles rows uA=ub and uB=432-ub; aggregated rows (289..432) pair
// with dense rows (0..143) and launch first.
__global__ __launch_bounds__(384) void k_out(const float* __restrict__ tk,
                                             const float* __restrict__ attn,
                                             float* __restrict__ out) {
    __shared__ float srow[2][PTOK];
    __shared__ int   cmap[RCOLS];
    const int ub   = blockIdx.x;                 // 0..216
    const int b    = blockIdx.y;
    const int t    = threadIdx.x;                // 384
    const int half = t / 192;
    const int lt   = t - half * 192;

    const int u = half ? (OUTROWS - 1 - ub) : ub;
    const bool active = (half == 0) || (u != ub);   // ub=216 -> same row twice
    const int row = g_rowmap[b][u];

    // stage this half's attention row (float4) + shared column map
    const float4* a4 = (const float4*)(attn + ((size_t)b * NTOK + row) * PTOK);
    if (lt < PTOK / 4) ((float4*)srow[half])[lt] = a4[lt];
    for (int v2 = t; v2 < RCOLS; v2 += 384) cmap[v2] = g_colmap[b][v2];

    // ---- token row: one float4 per thread of this half ----
    const float4* tk4 = (const float4*)tk;
    float4 v = tk4[((size_t)b * NTOK + row) * (DIM / 4) + lt];
    if (u > DENS) {                              // aggregated skip-selected row
        const int g  = u - 1 - DENS;
        const int st = g_selrange[b][g][0];
        const int en = g_selrange[b][g][1];
        float4 acc = make_float4(0.f, 0.f, 0.f, 0.f);
        for (int e = st; e < en; e++) {          // alive-only, ascending i
            float w  = g_ew[b][e];
            int   sr = g_ein[b][e];
            float4 sv = tk4[((size_t)b * NTOK + sr) * (DIM / 4) + lt];
            acc.x += w * sv.x; acc.y += w * sv.y;
            acc.z += w * sv.z; acc.w += w * sv.w;
        }
        v.x = acc.x + v.x; v.y = acc.y + v.y;
        v.z = acc.z + v.z; v.w = acc.w + v.w;
    }
    if (active)
        __stcs(((float4*)out) + ((size_t)b * OUTROWS + u) * (DIM / 4) + lt, v);

    // ---- R row: gather from SMEM, 16B streaming stores ----
    __syncthreads();
    if (active && lt < RCOLS / 4) {
        float4 r;
        r.x = srow[half][cmap[lt * 4 + 0]];
        r.y = srow[half][cmap[lt * 4 + 1]];
        r.z = srow[half][cmap[lt * 4 + 2]];
        r.w = srow[half][cmap[lt * 4 + 3]];
        float4* dst4 = (float4*)(out + (size_t)BATCH * OUTROWS * DIM
                                     + ((size_t)b * OUTROWS + u) * RCOLS);
        __stcs(dst4 + lt, r);
    }
}

// ---------------- launch ---------------------------------------------------
extern "C" void kernel_launch(void* const* d_in, const int* in_sizes, int n_in,
                              void* d_out, int out_size) {
    const float* tk   = (const float*)d_in[0];
    const float* attn = (const float*)d_in[1];
    float* out = (float*)d_out;

    k_order <<<dim3(4, BATCH), 192>>>(attn);
    k_top2  <<<dim3(SSZ / 8, BATCH), 256>>>(attn);
    k_graph2<<<BATCH, 288>>>(attn);
    k_out   <<<dim3((OUTROWS + 1) / 2, BATCH), 384>>>(tk, attn, out);
}

// round 10
// speedup vs baseline: 1.1067x; 1.1067x over previous
#include <cuda_runtime.h>

#define BATCH  64
#define NTOK   577
#define PTOK   576      // patches
#define DENS   288      // kept dense tokens
#define SSZ    288      // skipped tokens
#define GSZ    144      // selected group size
#define DIM    768
#define OUTROWS 433     // 1 + DENS + GSZ
#define RCOLS  432      // DENS + GSZ
#define EMAX   1200     // <= 4*288 = 1152 edges max

// ---------------- scratch (device globals; no allocation) ----------------
__device__ int   g_order[BATCH][PTOK];          // argsort(-cls_attn)
__device__ int   g_t2[BATCH][SSZ][2];           // top-2 neighbor per skip row
__device__ int   g_rowmap[BATCH][OUTROWS];      // attention/tk row index per output row
__device__ int   g_colmap[BATCH][RCOLS];        // attention col index per R column
__device__ int   g_ein[BATCH][EMAX];            // tk row index of edge source (alive only)
__device__ float g_ew[BATCH][EMAX];             // edge weight (alive only)
__device__ int   g_selrange[BATCH][GSZ][2];     // compacted [start,end) per selected node

// ---------------- kernel A: argsort(-cls_attn), stable, 4 segs/batch -------
__global__ __launch_bounds__(192) void k_order(const float* __restrict__ attn) {
    const int b   = blockIdx.y;
    const int seg = blockIdx.x;                 // 0..3 -> elements seg*144..+143
    __shared__ float a[PTOK];
    for (int p = threadIdx.x; p < PTOK; p += 192)
        a[p] = attn[(size_t)b * NTOK * PTOK + p];
    __syncthreads();
    if (threadIdx.x < 144) {
        const int p = seg * 144 + threadIdx.x;
        const float v = a[p];
        int r = 0;
        const float4* a4 = (const float4*)a;
        #pragma unroll 4
        for (int q4 = 0; q4 < PTOK / 4; q4++) {
            float4 u4 = a4[q4];
            int qb = q4 * 4;
            r += (u4.x > v) || (u4.x == v && qb     < p);
            r += (u4.y > v) || (u4.y == v && qb + 1 < p);
            r += (u4.z > v) || (u4.z == v && qb + 2 < p);
            r += (u4.w > v) || (u4.w == v && qb + 3 < p);
        }
        g_order[b][r] = p;                      // ranks are unique -> disjoint
    }
}

// ---------------- kernel B: top-2 per skip row (1 warp per row) ------------
__global__ __launch_bounds__(256) void k_top2(const float* __restrict__ attn) {
    const int b    = blockIdx.y;
    const int warp = threadIdx.x >> 5;          // 8 warps
    const int lane = threadIdx.x & 31;
    const int i    = blockIdx.x * 8 + warp;     // skip row index 0..287

    __shared__ int   ords[SSZ];
    __shared__ float rows[8][PTOK];

    for (int j = threadIdx.x; j < SSZ; j += 256) ords[j] = g_order[b][DENS + j];
    __syncthreads();

    const int ri = 1 + ords[i];
    const float4* src4 = (const float4*)(attn + ((size_t)b * NTOK + ri) * PTOK);
    #pragma unroll
    for (int k = 0; k < PTOK / 4 / 32 + 1; k++) {
        int p = lane + k * 32;
        if (p < PTOK / 4) ((float4*)rows[warp])[p] = src4[p];
    }
    __syncwarp();

    // local top-2 with key = (monotone(value), 287-j): tie -> smaller j wins
    unsigned long long k1 = 0ull, k2 = 0ull;
    #pragma unroll
    for (int k = 0; k < 9; k++) {
        int j = lane + k * 32;
        if (j == i) continue;
        float v = rows[warp][ords[j]];
        unsigned ub = __float_as_uint(v);
        ub ^= (unsigned)(((int)ub >> 31)) | 0x80000000u;   // total order on floats
        unsigned long long key = ((unsigned long long)ub << 32) | (unsigned)(SSZ - 1 - j);
        if (key > k1)      { k2 = k1; k1 = key; }
        else if (key > k2) { k2 = key; }
    }
    #pragma unroll
    for (int off = 16; off > 0; off >>= 1) {
        unsigned long long o1 = __shfl_down_sync(0xffffffffu, k1, off);
        unsigned long long o2 = __shfl_down_sync(0xffffffffu, k2, off);
        if (o1 > k1) { k2 = (k1 > o2) ? k1 : o2; k1 = o1; }
        else         { k2 = (k2 > o1) ? k2 : o1; }
    }
    if (lane == 0) {
        g_t2[b][i][0] = SSZ - 1 - (int)(k1 & 0xffffffffu);
        g_t2[b][i][1] = SSZ - 1 - (int)(k2 & 0xffffffffu);
    }
}

// ---- parallel exclusive scan over 288 per-thread values (288 threads) -----
__device__ __forceinline__ void scan288(int tid, int v, int* offs, int* wsum) {
    const int lane = tid & 31, warp = tid >> 5;     // 9 warps
    int incl = v;
    #pragma unroll
    for (int off = 1; off < 32; off <<= 1) {
        int n = __shfl_up_sync(0xffffffffu, incl, off);
        if (lane >= off) incl += n;
    }
    if (lane == 31) wsum[warp] = incl;
    __syncthreads();
    if (tid == 0) {
        int acc = 0;
        #pragma unroll
        for (int w = 0; w < 9; w++) { int t = wsum[w]; wsum[w] = acc; acc += t; }
        offs[SSZ] = acc;
    }
    __syncthreads();
    offs[tid] = incl - v + wsum[warp];
    __syncthreads();
}

// ---------------- kernel C: symmetrize + CSR + prune + select --------------
__global__ __launch_bounds__(288) void k_graph2(const float* __restrict__ attn) {
    const int b   = blockIdx.x;
    const int tid = threadIdx.x;                 // 288 threads
    const float* A0 = attn + (size_t)b * NTOK * PTOK;

    __shared__ int   order[PTOK];
    __shared__ unsigned colbits[SSZ * 9];        // bit i of colbits[j*9+(i>>5)] = edge i->j
    __shared__ int   offs[SSZ + 1];
    __shared__ int   coffs[SSZ + 1];
    __shared__ int   ein[EMAX];
    __shared__ float ew[EMAX];
    __shared__ unsigned char alive[EMAX];
    __shared__ float favg[2][SSZ];               // double-buffered averages
    __shared__ int   degi[SSZ];
    __shared__ int   gsel[GSZ];
    __shared__ int   wsum[9];

    for (int p = tid; p < PTOK; p += 288) order[p] = g_order[b][p];
    for (int k = tid; k < SSZ * 9; k += 288) colbits[k] = 0;
    __syncthreads();

    // symmetrize (column-major bit store)
    {
        const int i = tid;
        const int j1 = g_t2[b][i][0], j2 = g_t2[b][i][1];
        atomicOr(&colbits[j1 * 9 + (i >> 5)], 1u << (i & 31));   // i -> j1
        atomicOr(&colbits[j2 * 9 + (i >> 5)], 1u << (i & 31));   // i -> j2
        atomicOr(&colbits[i * 9 + (j1 >> 5)], 1u << (j1 & 31));  // j1 -> i
        atomicOr(&colbits[i * 9 + (j2 >> 5)], 1u << (j2 & 31));  // j2 -> i
    }
    __syncthreads();

    // per-column in-degree via popcount, then exclusive scan
    int mycnt = 0;
    #pragma unroll
    for (int w = 0; w < 9; w++) mycnt += __popc(colbits[tid * 9 + w]);
    scan288(tid, mycnt, offs, wsum);

    const int j   = tid;
    const int st0 = offs[j], en0 = offs[j + 1];

    // fill incoming CSR (i ascending within each j) via ffs walk. M = (W != 0)
    {
        const int cj = order[DENS + j];
        int ptr = st0;
        #pragma unroll
        for (int w = 0; w < 9; w++) {
            unsigned m = colbits[j * 9 + w];
            while (m) {
                int i = w * 32 + __ffs(m) - 1;
                m &= m - 1;
                float wv = A0[(size_t)(1 + order[DENS + i]) * PTOK + cj];
                ein[ptr] = i;
                ew[ptr]  = wv;
                alive[ptr] = (wv != 0.f) ? 1 : 0;
                ptr++;
            }
        }
    }

    // initial averages (own column only -> no barrier needed yet)
    int cur = 0;
    {
        int dg = 0; float s = 0.f;
        for (int e = st0; e < en0; e++)
            if (alive[e]) { dg++; s += ew[e]; }
        degi[j] = dg;
        favg[0][j] = (dg > 0) ? (s / (float)dg) : 0.f;
    }
    __syncthreads();                             // favg[0] visible to all

    // fixed point: ONE barrier-op per iteration
    for (;;) {
        const float aj = favg[cur][j];
        int ch = 0;
        for (int e = st0; e < en0; e++)
            if (alive[e] && !(aj > favg[cur][ein[e]])) { alive[e] = 0; ch = 1; }
        int dg = 0; float s = 0.f;
        for (int e = st0; e < en0; e++)
            if (alive[e]) { dg++; s += ew[e]; }
        degi[j] = dg;
        favg[cur ^ 1][j] = (dg > 0) ? (s / (float)dg) : 0.f;
        if (!__syncthreads_or(ch)) break;
        cur ^= 1;
    }
    // degi[j] == final alive in-degree

    // compacted offsets over final degrees
    scan288(tid, degi[tid], coffs, wsum);

    // top-144 by in-degree (ties -> smaller index first)
    {
        const int dj = degi[j];
        int r = 0;
        for (int q = 0; q < SSZ; q++) {
            int dq = degi[q];
            r += (dq > dj) || (dq == dj && q < j);
        }
        if (r < GSZ) gsel[r] = j;
    }

    // compacted alive edges to global (tk-row-resolved)
    {
        int ptr = coffs[j];
        for (int e = st0; e < en0; e++) {
            if (alive[e]) {
                g_ein[b][ptr] = 1 + order[DENS + ein[e]];
                g_ew[b][ptr]  = ew[e];
                ptr++;
            }
        }
    }
    __syncthreads();

    for (int g = tid; g < GSZ; g += 288) {
        int jj = gsel[g];
        g_selrange[b][g][0] = coffs[jj];
        g_selrange[b][g][1] = coffs[jj] + degi[jj];
    }
    for (int u = tid; u < OUTROWS; u += 288) {
        int row;
        if (u == 0)            row = 0;
        else if (u <= DENS)    row = 1 + order[u - 1];
        else                   row = 1 + order[DENS + gsel[u - 1 - DENS]];
        g_rowmap[b][u] = row;
    }
    for (int v = tid; v < RCOLS; v += 288) {
        int c;
        if (v < DENS) c = order[v];
        else          c = order[DENS + gsel[v - DENS]];
        g_colmap[b][v] = c;
    }
}

// -------- fused output kernel: 1 row/block, heavy rows first, 1 barrier ----
__global__ __launch_bounds__(192) void k_out(const float* __restrict__ tk,
                                             const float* __restrict__ attn,
                                             float* __restrict__ out) {
    __shared__ float srow[PTOK];
    __shared__ int   cmap[RCOLS];
    __shared__ int   s_sr[SSZ];
    __shared__ float s_w[SSZ];
    const int u = OUTROWS - 1 - blockIdx.x;      // aggregated (heavy) rows first
    const int b = blockIdx.y;
    const int t = threadIdx.x;                   // 192 threads
    const int row = g_rowmap[b][u];

    // ---- stage phase: attention row, column map, edge list ----
    const float4* a4 = (const float4*)(attn + ((size_t)b * NTOK + row) * PTOK);
    if (t < PTOK / 4) ((float4*)srow)[t] = a4[t];
    for (int v2 = t; v2 < RCOLS; v2 += 192) cmap[v2] = g_colmap[b][v2];

    int n = 0, st = 0;
    if (u > DENS) {
        const int g = u - 1 - DENS;
        st = g_selrange[b][g][0];
        n  = g_selrange[b][g][1] - st;
        for (int e = t; e < n; e += 192) {       // cooperative edge fetch
            s_sr[e] = g_ein[b][st + e];
            s_w[e]  = g_ew[b][st + e];
        }
    }
    __syncthreads();                             // the only barrier

    // ---- token row: one float4 per thread ----
    const float4* tk4 = (const float4*)tk;
    float4 v = tk4[((size_t)b * NTOK + row) * (DIM / 4) + t];
    if (u > DENS) {
        float4 acc = make_float4(0.f, 0.f, 0.f, 0.f);
        for (int e = 0; e < n; e++) {            // independent iterations (LDS src)
            float w  = s_w[e];
            int   sr = s_sr[e];
            float4 sv = tk4[((size_t)b * NTOK + sr) * (DIM / 4) + t];
            acc.x += w * sv.x; acc.y += w * sv.y;
            acc.z += w * sv.z; acc.w += w * sv.w;
        }
        v.x = acc.x + v.x; v.y = acc.y + v.y;
        v.z = acc.z + v.z; v.w = acc.w + v.w;
    }
    __stcs(((float4*)out) + ((size_t)b * OUTROWS + u) * (DIM / 4) + t, v);

    // ---- R row: gather from SMEM, 16B streaming stores ----
    if (t < RCOLS / 4) {
        float4 r;
        r.x = srow[cmap[t * 4 + 0]];
        r.y = srow[cmap[t * 4 + 1]];
        r.z = srow[cmap[t * 4 + 2]];
        r.w = srow[cmap[t * 4 + 3]];
        float4* dst4 = (float4*)(out + (size_t)BATCH * OUTROWS * DIM
                                     + ((size_t)b * OUTROWS + u) * RCOLS);
        __stcs(dst4 + t, r);
    }
}

// ---------------- launch ---------------------------------------------------
extern "C" void kernel_launch(void* const* d_in, const int* in_sizes, int n_in,
                              void* d_out, int out_size) {
    const float* tk   = (const float*)d_in[0];
    const float* attn = (const float*)d_in[1];
    float* out = (float*)d_out;

    k_order <<<dim3(4, BATCH), 192>>>(attn);
    k_top2  <<<dim3(SSZ / 8, BATCH), 256>>>(attn);
    k_graph2<<<BATCH, 288>>>(attn);
    k_out   <<<dim3(OUTROWS, BATCH), 192>>>(tk, attn, out);
}

// round 11
// speedup vs baseline: 1.2250x; 1.1069x over previous
#include <cuda_runtime.h>

#define BATCH  64
#define NTOK   577
#define PTOK   576      // patches
#define DENS   288      // kept dense tokens
#define SSZ    288      // skipped tokens
#define GSZ    144      // selected group size
#define DIM    768
#define OUTROWS 433     // 1 + DENS + GSZ
#define RCOLS  432      // DENS + GSZ
#define EMAX   1200     // <= 4*288 = 1152 edges max

// ---------------- scratch (device globals; no allocation) ----------------
__device__ int   g_order[BATCH][PTOK];          // argsort(-cls_attn)
__device__ int   g_t2[BATCH][SSZ][2];           // top-2 neighbor per skip row
__device__ int   g_rowmap[BATCH][OUTROWS];      // attention/tk row index per output row
__device__ int   g_colmap[BATCH][RCOLS];        // attention col index per R column
__device__ int   g_ein[BATCH][EMAX];            // tk row index of edge source (alive only)
__device__ float g_ew[BATCH][EMAX];             // edge weight (alive only)
__device__ int   g_selrange[BATCH][GSZ][2];     // compacted [start,end) per selected node

// ---------------- kernel A: argsort(-cls_attn), stable, 4 segs/batch -------
__global__ __launch_bounds__(192) void k_order(const float* __restrict__ attn) {
    const int b   = blockIdx.y;
    const int seg = blockIdx.x;                 // 0..3 -> elements seg*144..+143
    __shared__ float a[PTOK];
    for (int p = threadIdx.x; p < PTOK; p += 192)
        a[p] = attn[(size_t)b * NTOK * PTOK + p];
    __syncthreads();
    if (threadIdx.x < 144) {
        const int p = seg * 144 + threadIdx.x;
        const float v = a[p];
        int r = 0;
        const float4* a4 = (const float4*)a;
        #pragma unroll 4
        for (int q4 = 0; q4 < PTOK / 4; q4++) {
            float4 u4 = a4[q4];
            int qb = q4 * 4;
            r += (u4.x > v) || (u4.x == v && qb     < p);
            r += (u4.y > v) || (u4.y == v && qb + 1 < p);
            r += (u4.z > v) || (u4.z == v && qb + 2 < p);
            r += (u4.w > v) || (u4.w == v && qb + 3 < p);
        }
        g_order[b][r] = p;                      // ranks are unique -> disjoint
    }
}

// ---------------- kernel B: top-2 per skip row (1 warp per row) ------------
__global__ __launch_bounds__(256) void k_top2(const float* __restrict__ attn) {
    const int b    = blockIdx.y;
    const int warp = threadIdx.x >> 5;          // 8 warps
    const int lane = threadIdx.x & 31;
    const int i    = blockIdx.x * 8 + warp;     // skip row index 0..287

    __shared__ int   ords[SSZ];
    __shared__ float rows[8][PTOK];

    for (int j = threadIdx.x; j < SSZ; j += 256) ords[j] = g_order[b][DENS + j];
    __syncthreads();

    const int ri = 1 + ords[i];
    const float4* src4 = (const float4*)(attn + ((size_t)b * NTOK + ri) * PTOK);
    #pragma unroll
    for (int k = 0; k < PTOK / 4 / 32 + 1; k++) {
        int p = lane + k * 32;
        if (p < PTOK / 4) ((float4*)rows[warp])[p] = src4[p];
    }
    __syncwarp();

    // local top-2 with key = (monotone(value), 287-j): tie -> smaller j wins
    unsigned long long k1 = 0ull, k2 = 0ull;
    #pragma unroll
    for (int k = 0; k < 9; k++) {
        int j = lane + k * 32;
        if (j == i) continue;
        float v = rows[warp][ords[j]];
        unsigned ub = __float_as_uint(v);
        ub ^= (unsigned)(((int)ub >> 31)) | 0x80000000u;   // total order on floats
        unsigned long long key = ((unsigned long long)ub << 32) | (unsigned)(SSZ - 1 - j);
        if (key > k1)      { k2 = k1; k1 = key; }
        else if (key > k2) { k2 = key; }
    }
    #pragma unroll
    for (int off = 16; off > 0; off >>= 1) {
        unsigned long long o1 = __shfl_down_sync(0xffffffffu, k1, off);
        unsigned long long o2 = __shfl_down_sync(0xffffffffu, k2, off);
        if (o1 > k1) { k2 = (k1 > o2) ? k1 : o2; k1 = o1; }
        else         { k2 = (k2 > o1) ? k2 : o1; }
    }
    if (lane == 0) {
        g_t2[b][i][0] = SSZ - 1 - (int)(k1 & 0xffffffffu);
        g_t2[b][i][1] = SSZ - 1 - (int)(k2 & 0xffffffffu);
    }
}

// ---- parallel exclusive scan over 288 per-thread values (288 threads) -----
__device__ __forceinline__ void scan288(int tid, int v, int* offs, int* wsum) {
    const int lane = tid & 31, warp = tid >> 5;     // 9 warps
    int incl = v;
    #pragma unroll
    for (int off = 1; off < 32; off <<= 1) {
        int n = __shfl_up_sync(0xffffffffu, incl, off);
        if (lane >= off) incl += n;
    }
    if (lane == 31) wsum[warp] = incl;
    __syncthreads();
    if (tid == 0) {
        int acc = 0;
        #pragma unroll
        for (int w = 0; w < 9; w++) { int t = wsum[w]; wsum[w] = acc; acc += t; }
        offs[SSZ] = acc;
    }
    __syncthreads();
    offs[tid] = incl - v + wsum[warp];
    __syncthreads();
}

// ---------------- kernel C: symmetrize + CSR + prune + select --------------
__global__ __launch_bounds__(288) void k_graph2(const float* __restrict__ attn) {
    const int b   = blockIdx.x;
    const int tid = threadIdx.x;                 // 288 threads
    const float* A0 = attn + (size_t)b * NTOK * PTOK;

    __shared__ int   order[PTOK];
    __shared__ unsigned colbits[SSZ * 9];        // bit i of colbits[j*9+(i>>5)] = edge i->j
    __shared__ int   offs[SSZ + 1];
    __shared__ int   coffs[SSZ + 1];
    __shared__ int   ein[EMAX];
    __shared__ float ew[EMAX];
    __shared__ unsigned char alive[EMAX];
    __shared__ float favg[2][SSZ];               // double-buffered averages
    __shared__ int   degi[SSZ];
    __shared__ int   gsel[GSZ];
    __shared__ int   wsum[9];

    for (int p = tid; p < PTOK; p += 288) order[p] = g_order[b][p];
    for (int k = tid; k < SSZ * 9; k += 288) colbits[k] = 0;
    __syncthreads();

    // symmetrize (column-major bit store)
    {
        const int i = tid;
        const int j1 = g_t2[b][i][0], j2 = g_t2[b][i][1];
        atomicOr(&colbits[j1 * 9 + (i >> 5)], 1u << (i & 31));   // i -> j1
        atomicOr(&colbits[j2 * 9 + (i >> 5)], 1u << (i & 31));   // i -> j2
        atomicOr(&colbits[i * 9 + (j1 >> 5)], 1u << (j1 & 31));  // j1 -> i
        atomicOr(&colbits[i * 9 + (j2 >> 5)], 1u << (j2 & 31));  // j2 -> i
    }
    __syncthreads();

    // per-column in-degree via popcount, then exclusive scan
    int mycnt = 0;
    #pragma unroll
    for (int w = 0; w < 9; w++) mycnt += __popc(colbits[tid * 9 + w]);
    scan288(tid, mycnt, offs, wsum);

    const int j   = tid;
    const int st0 = offs[j], en0 = offs[j + 1];

    // fill incoming CSR (i ascending within each j) via ffs walk. M = (W != 0)
    {
        const int cj = order[DENS + j];
        int ptr = st0;
        #pragma unroll
        for (int w = 0; w < 9; w++) {
            unsigned m = colbits[j * 9 + w];
            while (m) {
                int i = w * 32 + __ffs(m) - 1;
                m &= m - 1;
                float wv = A0[(size_t)(1 + order[DENS + i]) * PTOK + cj];
                ein[ptr] = i;
                ew[ptr]  = wv;
                alive[ptr] = (wv != 0.f) ? 1 : 0;
                ptr++;
            }
        }
    }

    // initial averages (own column only -> no barrier needed yet)
    int cur = 0;
    {
        int dg = 0; float s = 0.f;
        for (int e = st0; e < en0; e++)
            if (alive[e]) { dg++; s += ew[e]; }
        degi[j] = dg;
        favg[0][j] = (dg > 0) ? (s / (float)dg) : 0.f;
    }
    __syncthreads();                             // favg[0] visible to all

    // fixed point: ONE barrier-op per iteration
    for (;;) {
        const float aj = favg[cur][j];
        int ch = 0;
        for (int e = st0; e < en0; e++)
            if (alive[e] && !(aj > favg[cur][ein[e]])) { alive[e] = 0; ch = 1; }
        int dg = 0; float s = 0.f;
        for (int e = st0; e < en0; e++)
            if (alive[e]) { dg++; s += ew[e]; }
        degi[j] = dg;
        favg[cur ^ 1][j] = (dg > 0) ? (s / (float)dg) : 0.f;
        if (!__syncthreads_or(ch)) break;
        cur ^= 1;
    }
    // degi[j] == final alive in-degree

    // compacted offsets over final degrees
    scan288(tid, degi[tid], coffs, wsum);

    // top-144 by in-degree (ties -> smaller index first)
    {
        const int dj = degi[j];
        int r = 0;
        for (int q = 0; q < SSZ; q++) {
            int dq = degi[q];
            r += (dq > dj) || (dq == dj && q < j);
        }
        if (r < GSZ) gsel[r] = j;
    }

    // compacted alive edges to global (tk-row-resolved)
    {
        int ptr = coffs[j];
        for (int e = st0; e < en0; e++) {
            if (alive[e]) {
                g_ein[b][ptr] = 1 + order[DENS + ein[e]];
                g_ew[b][ptr]  = ew[e];
                ptr++;
            }
        }
    }
    __syncthreads();

    for (int g = tid; g < GSZ; g += 288) {
        int jj = gsel[g];
        g_selrange[b][g][0] = coffs[jj];
        g_selrange[b][g][1] = coffs[jj] + degi[jj];
    }
    for (int u = tid; u < OUTROWS; u += 288) {
        int row;
        if (u == 0)            row = 0;
        else if (u <= DENS)    row = 1 + order[u - 1];
        else                   row = 1 + order[DENS + gsel[u - 1 - DENS]];
        g_rowmap[b][u] = row;
    }
    for (int v = tid; v < RCOLS; v += 288) {
        int c;
        if (v < DENS) c = order[v];
        else          c = order[DENS + gsel[v - DENS]];
        g_colmap[b][v] = c;
    }
}

// -------- fused output kernel: 1 row/block, heavy rows first ---------------
__global__ __launch_bounds__(192) void k_out(const float* __restrict__ tk,
                                             const float* __restrict__ attn,
                                             float* __restrict__ out) {
    __shared__ float srow[PTOK];
    __shared__ int   cmap[RCOLS];
    const int u = OUTROWS - 1 - blockIdx.x;      // aggregated (heavy) rows first
    const int b = blockIdx.y;
    const int t = threadIdx.x;                   // 192 threads
    const int row = g_rowmap[b][u];

    // stage attention row (float4) + column map early
    const float4* a4 = (const float4*)(attn + ((size_t)b * NTOK + row) * PTOK);
    if (t < PTOK / 4) ((float4*)srow)[t] = a4[t];
    for (int v2 = t; v2 < RCOLS; v2 += 192) cmap[v2] = g_colmap[b][v2];

    // ---- tokens: one float4 per thread ----
    const float4* tk4 = (const float4*)tk;
    float4 v = tk4[((size_t)b * NTOK + row) * (DIM / 4) + t];
    if (u > DENS) {                              // aggregated skip-selected rows
        const int g = u - 1 - DENS;
        const int st = g_selrange[b][g][0];
        const int en = g_selrange[b][g][1];
        float4 acc = make_float4(0.f, 0.f, 0.f, 0.f);
        for (int e = st; e < en; e++) {          // alive-only, branch-free body
            float w  = g_ew[b][e];
            int   sr = g_ein[b][e];
            float4 sv = tk4[((size_t)b * NTOK + sr) * (DIM / 4) + t];
            acc.x += w * sv.x; acc.y += w * sv.y;
            acc.z += w * sv.z; acc.w += w * sv.w;
        }
        v.x = acc.x + v.x; v.y = acc.y + v.y;
        v.z = acc.z + v.z; v.w = acc.w + v.w;
    }
    __stcs(((float4*)out) + ((size_t)b * OUTROWS + u) * (DIM / 4) + t, v);

    // ---- R row: gather from SMEM, 16B streaming stores ----
    __syncthreads();
    if (t < RCOLS / 4) {
        float4 r;
        r.x = srow[cmap[t * 4 + 0]];
        r.y = srow[cmap[t * 4 + 1]];
        r.z = srow[cmap[t * 4 + 2]];
        r.w = srow[cmap[t * 4 + 3]];
        float4* dst4 = (float4*)(out + (size_t)BATCH * OUTROWS * DIM
                                     + ((size_t)b * OUTROWS + u) * RCOLS);
        __stcs(dst4 + t, r);
    }
}

// ---------------- launch ---------------------------------------------------
extern "C" void kernel_launch(void* const* d_in, const int* in_sizes, int n_in,
                              void* d_out, int out_size) {
    const float* tk   = (const float*)d_in[0];
    const float* attn = (const float*)d_in[1];
    float* out = (float*)d_out;

    k_order <<<dim3(4, BATCH), 192>>>(attn);
    k_top2  <<<dim3(SSZ / 8, BATCH), 256>>>(attn);
    k_graph2<<<BATCH, 288>>>(attn);
    k_out   <<<dim3(OUTROWS, BATCH), 192>>>(tk, attn, out);
}

// round 12
// speedup vs baseline: 1.2971x; 1.0589x over previous
#include <cuda_runtime.h>

#define BATCH  64
#define NTOK   577
#define PTOK   576      // patches
#define DENS   288      // kept dense tokens
#define SSZ    288      // skipped tokens
#define GSZ    144      // selected group size
#define DIM    768
#define OUTROWS 433     // 1 + DENS + GSZ
#define RCOLS  432      // DENS + GSZ
#define EMAX   1200     // <= 4*288 = 1152 edges max
#define NREG   16       // register-cached edges per column

// ---------------- scratch (device globals; no allocation) ----------------
__device__ int            g_order[BATCH][PTOK];     // argsort(-cls_attn)
__device__ int            g_t2[BATCH][SSZ][2];      // top-2 neighbor per skip row
__device__ int            g_rowmap[BATCH][OUTROWS]; // attention/tk row per output row
__device__ unsigned short g_colmap[BATCH][RCOLS];   // attention col per R column
__device__ int            g_ein[BATCH][EMAX];       // tk row of edge source (alive only)
__device__ float          g_ew[BATCH][EMAX];        // edge weight (alive only)
__device__ int            g_selrange[BATCH][GSZ][2];// compacted [start,end) per sel node

// ---------------- kernel A: argsort(-cls_attn), stable, 4 segs/batch -------
__global__ __launch_bounds__(192) void k_order(const float* __restrict__ attn) {
    const int b   = blockIdx.y;
    const int seg = blockIdx.x;                 // 0..3 -> elements seg*144..+143
    __shared__ float a[PTOK];
    for (int p = threadIdx.x; p < PTOK; p += 192)
        a[p] = attn[(size_t)b * NTOK * PTOK + p];
    __syncthreads();
    if (threadIdx.x < 144) {
        const int p = seg * 144 + threadIdx.x;
        const float v = a[p];
        int r = 0;
        const float4* a4 = (const float4*)a;
        #pragma unroll 4
        for (int q4 = 0; q4 < PTOK / 4; q4++) {
            float4 u4 = a4[q4];
            int qb = q4 * 4;
            r += (u4.x > v) || (u4.x == v && qb     < p);
            r += (u4.y > v) || (u4.y == v && qb + 1 < p);
            r += (u4.z > v) || (u4.z == v && qb + 2 < p);
            r += (u4.w > v) || (u4.w == v && qb + 3 < p);
        }
        g_order[b][r] = p;                      // ranks are unique -> disjoint
    }
}

// ---------------- kernel B: top-2 per skip row (1 warp per row) ------------
__global__ __launch_bounds__(256) void k_top2(const float* __restrict__ attn) {
    const int b    = blockIdx.y;
    const int warp = threadIdx.x >> 5;          // 8 warps
    const int lane = threadIdx.x & 31;
    const int i    = blockIdx.x * 8 + warp;     // skip row index 0..287

    __shared__ int   ords[SSZ];
    __shared__ float rows[8][PTOK];

    for (int j = threadIdx.x; j < SSZ; j += 256) ords[j] = g_order[b][DENS + j];
    __syncthreads();

    const int ri = 1 + ords[i];
    const float4* src4 = (const float4*)(attn + ((size_t)b * NTOK + ri) * PTOK);
    #pragma unroll
    for (int k = 0; k < PTOK / 4 / 32 + 1; k++) {
        int p = lane + k * 32;
        if (p < PTOK / 4) ((float4*)rows[warp])[p] = src4[p];
    }
    __syncwarp();

    // local top-2 with key = (monotone(value), 287-j): tie -> smaller j wins
    unsigned long long k1 = 0ull, k2 = 0ull;
    #pragma unroll
    for (int k = 0; k < 9; k++) {
        int j = lane + k * 32;
        if (j == i) continue;
        float v = rows[warp][ords[j]];
        unsigned ub = __float_as_uint(v);
        ub ^= (unsigned)(((int)ub >> 31)) | 0x80000000u;   // total order on floats
        unsigned long long key = ((unsigned long long)ub << 32) | (unsigned)(SSZ - 1 - j);
        if (key > k1)      { k2 = k1; k1 = key; }
        else if (key > k2) { k2 = key; }
    }
    #pragma unroll
    for (int off = 16; off > 0; off >>= 1) {
        unsigned long long o1 = __shfl_down_sync(0xffffffffu, k1, off);
        unsigned long long o2 = __shfl_down_sync(0xffffffffu, k2, off);
        if (o1 > k1) { k2 = (k1 > o2) ? k1 : o2; k1 = o1; }
        else         { k2 = (k2 > o1) ? k2 : o1; }
    }
    if (lane == 0) {
        g_t2[b][i][0] = SSZ - 1 - (int)(k1 & 0xffffffffu);
        g_t2[b][i][1] = SSZ - 1 - (int)(k2 & 0xffffffffu);
    }
}

// ---- parallel exclusive scan over 288 per-thread values (288 threads) -----
__device__ __forceinline__ void scan288(int tid, int v, int* offs, int* wsum) {
    const int lane = tid & 31, warp = tid >> 5;     // 9 warps
    int incl = v;
    #pragma unroll
    for (int off = 1; off < 32; off <<= 1) {
        int n = __shfl_up_sync(0xffffffffu, incl, off);
        if (lane >= off) incl += n;
    }
    if (lane == 31) wsum[warp] = incl;
    __syncthreads();
    if (tid == 0) {
        int acc = 0;
        #pragma unroll
        for (int w = 0; w < 9; w++) { int t = wsum[w]; wsum[w] = acc; acc += t; }
        offs[SSZ] = acc;
    }
    __syncthreads();
    offs[tid] = incl - v + wsum[warp];
    __syncthreads();
}

// ---------------- kernel C: symmetrize + CSR + prune + select --------------
__global__ __launch_bounds__(288) void k_graph2(const float* __restrict__ attn) {
    const int b   = blockIdx.x;
    const int tid = threadIdx.x;                 // 288 threads
    const float* A0 = attn + (size_t)b * NTOK * PTOK;

    __shared__ int   order[PTOK];
    __shared__ unsigned colbits[SSZ * 9];        // bit i of colbits[j*9+(i>>5)] = edge i->j
    __shared__ int   offs[SSZ + 1];
    __shared__ int   coffs[SSZ + 1];
    __shared__ int   ein[EMAX];
    __shared__ float ew[EMAX];
    __shared__ unsigned char alive[EMAX];        // used only for overflow (deg>NREG)
    __shared__ float favg[2][SSZ];               // double-buffered averages
    __shared__ int   degi[SSZ];
    __shared__ int   gsel[GSZ];
    __shared__ int   wsum[9];

    for (int p = tid; p < PTOK; p += 288) order[p] = g_order[b][p];
    for (int k = tid; k < SSZ * 9; k += 288) colbits[k] = 0;
    __syncthreads();

    // symmetrize (column-major bit store)
    {
        const int i = tid;
        const int j1 = g_t2[b][i][0], j2 = g_t2[b][i][1];
        atomicOr(&colbits[j1 * 9 + (i >> 5)], 1u << (i & 31));   // i -> j1
        atomicOr(&colbits[j2 * 9 + (i >> 5)], 1u << (i & 31));   // i -> j2
        atomicOr(&colbits[i * 9 + (j1 >> 5)], 1u << (j1 & 31));  // j1 -> i
        atomicOr(&colbits[i * 9 + (j2 >> 5)], 1u << (j2 & 31));  // j2 -> i
    }
    __syncthreads();

    // per-column in-degree via popcount, then exclusive scan
    int mycnt = 0;
    #pragma unroll
    for (int w = 0; w < 9; w++) mycnt += __popc(colbits[tid * 9 + w]);
    scan288(tid, mycnt, offs, wsum);

    const int j    = tid;
    const int st0  = offs[j], en0 = offs[j + 1];
    const int deg0 = en0 - st0;

    // fill incoming CSR (i ascending within each j) via ffs walk. M = (W != 0)
    {
        const int cj = order[DENS + j];
        int ptr = st0;
        #pragma unroll
        for (int w = 0; w < 9; w++) {
            unsigned m = colbits[j * 9 + w];
            while (m) {
                int i = w * 32 + __ffs(m) - 1;
                m &= m - 1;
                float wv = A0[(size_t)(1 + order[DENS + i]) * PTOK + cj];
                ein[ptr] = i;
                ew[ptr]  = wv;
                alive[ptr] = (wv != 0.f) ? 1 : 0;
                ptr++;
            }
        }
    }

    // cache first NREG edges in registers (constant indices -> true registers)
    int   srcR[NREG];
    float wR[NREG];
    unsigned am = 0;                              // alive bitmask, bit k = edge k
    #pragma unroll
    for (int k = 0; k < NREG; k++) {
        bool in = (k < deg0);
        srcR[k] = in ? ein[st0 + k] : 0;
        wR[k]   = in ? ew[st0 + k] : 0.f;
        if (in && wR[k] != 0.f) am |= (1u << k);
    }
    const int ovfEnd = en0;                       // overflow edges: st0+NREG..en0

    // initial averages (ascending-i order preserved: regs first, then overflow)
    int cur = 0;
    {
        int dg = 0; float s = 0.f;
        #pragma unroll
        for (int k = 0; k < NREG; k++)
            if (am & (1u << k)) { dg++; s += wR[k]; }
        for (int e = st0 + NREG; e < ovfEnd; e++)
            if (alive[e]) { dg++; s += ew[e]; }
        degi[j] = dg;
        favg[0][j] = (dg > 0) ? (s / (float)dg) : 0.f;
    }
    __syncthreads();                             // favg[0] visible to all

    // fixed point: ONE barrier-op per iteration, register-resident edges
    for (;;) {
        const float aj = favg[cur][j];
        int ch = 0;
        #pragma unroll
        for (int k = 0; k < NREG; k++) {
            if (am & (1u << k)) {
                if (!(aj > favg[cur][srcR[k]])) { am &= ~(1u << k); ch = 1; }
            }
        }
        for (int e = st0 + NREG; e < ovfEnd; e++)
            if (alive[e] && !(aj > favg[cur][ein[e]])) { alive[e] = 0; ch = 1; }
        int dg = 0; float s = 0.f;
        #pragma unroll
        for (int k = 0; k < NREG; k++)
            if (am & (1u << k)) { dg++; s += wR[k]; }
        for (int e = st0 + NREG; e < ovfEnd; e++)
            if (alive[e]) { dg++; s += ew[e]; }
        degi[j] = dg;
        favg[cur ^ 1][j] = (dg > 0) ? (s / (float)dg) : 0.f;
        if (!__syncthreads_or(ch)) break;
        cur ^= 1;
    }
    // degi[j] == final alive in-degree

    // compacted offsets over final degrees
    scan288(tid, degi[tid], coffs, wsum);

    // top-144 by in-degree (ties -> smaller index first)
    {
        const int dj = degi[j];
        int r = 0;
        for (int q = 0; q < SSZ; q++) {
            int dq = degi[q];
            r += (dq > dj) || (dq == dj && q < j);
        }
        if (r < GSZ) gsel[r] = j;
    }

    // compacted alive edges to global (tk-row-resolved), ascending i
    {
        int ptr = coffs[j];
        #pragma unroll
        for (int k = 0; k < NREG; k++) {
            if (am & (1u << k)) {
                g_ein[b][ptr] = 1 + order[DENS + srcR[k]];
                g_ew[b][ptr]  = wR[k];
                ptr++;
            }
        }
        for (int e = st0 + NREG; e < ovfEnd; e++) {
            if (alive[e]) {
                g_ein[b][ptr] = 1 + order[DENS + ein[e]];
                g_ew[b][ptr]  = ew[e];
                ptr++;
            }
        }
    }
    __syncthreads();

    for (int g = tid; g < GSZ; g += 288) {
        int jj = gsel[g];
        g_selrange[b][g][0] = coffs[jj];
        g_selrange[b][g][1] = coffs[jj] + degi[jj];
    }
    for (int u = tid; u < OUTROWS; u += 288) {
        int row;
        if (u == 0)            row = 0;
        else if (u <= DENS)    row = 1 + order[u - 1];
        else                   row = 1 + order[DENS + gsel[u - 1 - DENS]];
        g_rowmap[b][u] = row;
    }
    for (int v = tid; v < RCOLS; v += 288) {
        int c;
        if (v < DENS) c = order[v];
        else          c = order[DENS + gsel[v - DENS]];
        g_colmap[b][v] = (unsigned short)c;
    }
}

// -------- fused output kernel: 1 row/block, heavy rows first ---------------
__global__ __launch_bounds__(192) void k_out(const float* __restrict__ tk,
                                             const float* __restrict__ attn,
                                             float* __restrict__ out) {
    __shared__ float srow[PTOK];
    __shared__ unsigned short cmap[RCOLS];
    const int u = OUTROWS - 1 - blockIdx.x;      // aggregated (heavy) rows first
    const int b = blockIdx.y;
    const int t = threadIdx.x;                   // 192 threads
    const int row = g_rowmap[b][u];

    // stage attention row (float4) + column map early
    const float4* a4 = (const float4*)(attn + ((size_t)b * NTOK + row) * PTOK);
    if (t < PTOK / 4) ((float4*)srow)[t] = a4[t];
    for (int v2 = t; v2 < RCOLS; v2 += 192) cmap[v2] = g_colmap[b][v2];

    // ---- tokens: one float4 per thread ----
    const float4* tk4 = (const float4*)tk;
    float4 v = tk4[((size_t)b * NTOK + row) * (DIM / 4) + t];
    if (u > DENS) {                              // aggregated skip-selected rows
        const int g = u - 1 - DENS;
        const int st = g_selrange[b][g][0];
        const int en = g_selrange[b][g][1];
        float4 acc = make_float4(0.f, 0.f, 0.f, 0.f);
        for (int e = st; e < en; e++) {          // alive-only, branch-free body
            float w  = g_ew[b][e];
            int   sr = g_ein[b][e];
            float4 sv = tk4[((size_t)b * NTOK + sr) * (DIM / 4) + t];
            acc.x += w * sv.x; acc.y += w * sv.y;
            acc.z += w * sv.z; acc.w += w * sv.w;
        }
        v.x = acc.x + v.x; v.y = acc.y + v.y;
        v.z = acc.z + v.z; v.w = acc.w + v.w;
    }
    __stcs(((float4*)out) + ((size_t)b * OUTROWS + u) * (DIM / 4) + t, v);

    // ---- R row: gather from SMEM, 16B streaming stores ----
    __syncthreads();
    if (t < RCOLS / 4) {
        float4 r;
        r.x = srow[cmap[t * 4 + 0]];
        r.y = srow[cmap[t * 4 + 1]];
        r.z = srow[cmap[t * 4 + 2]];
        r.w = srow[cmap[t * 4 + 3]];
        float4* dst4 = (float4*)(out + (size_t)BATCH * OUTROWS * DIM
                                     + ((size_t)b * OUTROWS + u) * RCOLS);
        __stcs(dst4 + t, r);
    }
}

// ---------------- launch ---------------------------------------------------
extern "C" void kernel_launch(void* const* d_in, const int* in_sizes, int n_in,
                              void* d_out, int out_size) {
    const float* tk   = (const float*)d_in[0];
    const float* attn = (const float*)d_in[1];
    float* out = (float*)d_out;

    k_order <<<dim3(4, BATCH), 192>>>(attn);
    k_top2  <<<dim3(SSZ / 8, BATCH), 256>>>(attn);
    k_graph2<<<BATCH, 288>>>(attn);
    k_out   <<<dim3(OUTROWS, BATCH), 192>>>(tk, attn, out);
}

// round 13
// speedup vs baseline: 1.3909x; 1.0723x over previous
#include <cuda_runtime.h>

#define BATCH  64
#define NTOK   577
#define PTOK   576      // patches
#define DENS   288      // kept dense tokens
#define SSZ    288      // skipped tokens
#define GSZ    144      // selected group size
#define DIM    768
#define OUTROWS 433     // 1 + DENS + GSZ
#define RCOLS  432      // DENS + GSZ
#define EMAX   1200     // <= 4*288 = 1152 edges max
#define NREG   16       // register-cached edges per column

// ---------------- scratch (device globals; no allocation) ----------------
__device__ int            g_order[BATCH][PTOK];     // argsort(-cls_attn)
__device__ int            g_t2[BATCH][SSZ][2];      // top-2 neighbor per skip row
__device__ int            g_rowmap[BATCH][OUTROWS]; // attention/tk row per output row
__device__ unsigned short g_colmap[BATCH][RCOLS];   // attention col per R column
__device__ int            g_ein[BATCH][EMAX];       // tk row of edge source (alive only)
__device__ float          g_ew[BATCH][EMAX];        // edge weight (alive only)
__device__ int            g_selrange[BATCH][GSZ][2];// compacted [start,end) per sel node

// ---------------- kernel A: argsort(-cls_attn), stable, 4 segs/batch -------
__global__ __launch_bounds__(192) void k_order(const float* __restrict__ attn) {
    const int b   = blockIdx.y;
    const int seg = blockIdx.x;                 // 0..3 -> elements seg*144..+143
    __shared__ float a[PTOK];
    for (int p = threadIdx.x; p < PTOK; p += 192)
        a[p] = attn[(size_t)b * NTOK * PTOK + p];
    __syncthreads();
    if (threadIdx.x < 144) {
        const int p = seg * 144 + threadIdx.x;
        const float v = a[p];
        int r = 0;
        const float4* a4 = (const float4*)a;
        #pragma unroll 4
        for (int q4 = 0; q4 < PTOK / 4; q4++) {
            float4 u4 = a4[q4];
            int qb = q4 * 4;
            r += (u4.x > v) || (u4.x == v && qb     < p);
            r += (u4.y > v) || (u4.y == v && qb + 1 < p);
            r += (u4.z > v) || (u4.z == v && qb + 2 < p);
            r += (u4.w > v) || (u4.w == v && qb + 3 < p);
        }
        g_order[b][r] = p;                      // ranks are unique -> disjoint
    }
}

// ---------------- kernel B: top-2 per skip row (1 warp per row) ------------
__global__ __launch_bounds__(256) void k_top2(const float* __restrict__ attn) {
    const int b    = blockIdx.y;
    const int warp = threadIdx.x >> 5;          // 8 warps
    const int lane = threadIdx.x & 31;
    const int i    = blockIdx.x * 8 + warp;     // skip row index 0..287

    __shared__ int   ords[SSZ];
    __shared__ float rows[8][PTOK];

    for (int j = threadIdx.x; j < SSZ; j += 256) ords[j] = g_order[b][DENS + j];
    __syncthreads();

    const int ri = 1 + ords[i];
    const float4* src4 = (const float4*)(attn + ((size_t)b * NTOK + ri) * PTOK);
    #pragma unroll
    for (int k = 0; k < PTOK / 4 / 32 + 1; k++) {
        int p = lane + k * 32;
        if (p < PTOK / 4) ((float4*)rows[warp])[p] = src4[p];
    }
    __syncwarp();

    // local top-2 with key = (monotone(value), 287-j): tie -> smaller j wins
    unsigned long long k1 = 0ull, k2 = 0ull;
    #pragma unroll
    for (int k = 0; k < 9; k++) {
        int j = lane + k * 32;
        if (j == i) continue;
        float v = rows[warp][ords[j]];
        unsigned ub = __float_as_uint(v);
        ub ^= (unsigned)(((int)ub >> 31)) | 0x80000000u;   // total order on floats
        unsigned long long key = ((unsigned long long)ub << 32) | (unsigned)(SSZ - 1 - j);
        if (key > k1)      { k2 = k1; k1 = key; }
        else if (key > k2) { k2 = key; }
    }
    #pragma unroll
    for (int off = 16; off > 0; off >>= 1) {
        unsigned long long o1 = __shfl_down_sync(0xffffffffu, k1, off);
        unsigned long long o2 = __shfl_down_sync(0xffffffffu, k2, off);
        if (o1 > k1) { k2 = (k1 > o2) ? k1 : o2; k1 = o1; }
        else         { k2 = (k2 > o1) ? k2 : o1; }
    }
    if (lane == 0) {
        g_t2[b][i][0] = SSZ - 1 - (int)(k1 & 0xffffffffu);
        g_t2[b][i][1] = SSZ - 1 - (int)(k2 & 0xffffffffu);
    }
}

// ---- parallel exclusive scan over 288 per-thread values (288 threads) -----
__device__ __forceinline__ void scan288(int tid, int v, int* offs, int* wsum) {
    const int lane = tid & 31, warp = tid >> 5;     // 9 warps
    int incl = v;
    #pragma unroll
    for (int off = 1; off < 32; off <<= 1) {
        int n = __shfl_up_sync(0xffffffffu, incl, off);
        if (lane >= off) incl += n;
    }
    if (lane == 31) wsum[warp] = incl;
    __syncthreads();
    if (tid == 0) {
        int acc = 0;
        #pragma unroll
        for (int w = 0; w < 9; w++) { int t = wsum[w]; wsum[w] = acc; acc += t; }
        offs[SSZ] = acc;
    }
    __syncthreads();
    offs[tid] = incl - v + wsum[warp];
    __syncthreads();
}

// ---------------- kernel C: symmetrize + CSR + prune + select --------------
__global__ __launch_bounds__(288) void k_graph2(const float* __restrict__ attn) {
    const int b   = blockIdx.x;
    const int tid = threadIdx.x;                 // 288 threads
    const float* A0 = attn + (size_t)b * NTOK * PTOK;

    __shared__ int   order[PTOK];
    __shared__ unsigned colbits[SSZ * 9];        // bit i of colbits[j*9+(i>>5)] = edge i->j
    __shared__ int   offs[SSZ + 1];
    __shared__ int   coffs[SSZ + 1];
    __shared__ int   ein[EMAX];
    __shared__ float ew[EMAX];
    __shared__ unsigned char alive[EMAX];        // used only for overflow (deg>NREG)
    __shared__ float favg[2][SSZ];               // double-buffered averages
    __shared__ __align__(16) int degi[SSZ];
    __shared__ int   gsel[GSZ];
    __shared__ int   wsum[9];

    for (int p = tid; p < PTOK; p += 288) order[p] = g_order[b][p];
    for (int k = tid; k < SSZ * 9; k += 288) colbits[k] = 0;
    __syncthreads();

    // symmetrize (column-major bit store)
    {
        const int i = tid;
        const int j1 = g_t2[b][i][0], j2 = g_t2[b][i][1];
        atomicOr(&colbits[j1 * 9 + (i >> 5)], 1u << (i & 31));   // i -> j1
        atomicOr(&colbits[j2 * 9 + (i >> 5)], 1u << (i & 31));   // i -> j2
        atomicOr(&colbits[i * 9 + (j1 >> 5)], 1u << (j1 & 31));  // j1 -> i
        atomicOr(&colbits[i * 9 + (j2 >> 5)], 1u << (j2 & 31));  // j2 -> i
    }
    __syncthreads();

    // per-column in-degree via popcount, then exclusive scan
    int mycnt = 0;
    #pragma unroll
    for (int w = 0; w < 9; w++) mycnt += __popc(colbits[tid * 9 + w]);
    scan288(tid, mycnt, offs, wsum);

    const int j    = tid;
    const int st0  = offs[j], en0 = offs[j + 1];
    const int deg0 = en0 - st0;

    // fill incoming CSR (i ascending within each j) via ffs walk. M = (W != 0)
    {
        const int cj = order[DENS + j];
        int ptr = st0;
        #pragma unroll
        for (int w = 0; w < 9; w++) {
            unsigned m = colbits[j * 9 + w];
            while (m) {
                int i = w * 32 + __ffs(m) - 1;
                m &= m - 1;
                float wv = A0[(size_t)(1 + order[DENS + i]) * PTOK + cj];
                ein[ptr] = i;
                ew[ptr]  = wv;
                alive[ptr] = (wv != 0.f) ? 1 : 0;
                ptr++;
            }
        }
    }

    // cache first NREG edges in registers (constant indices -> true registers)
    int   srcR[NREG];
    float wR[NREG];
    unsigned am = 0;                              // alive bitmask, bit k = edge k
    #pragma unroll
    for (int k = 0; k < NREG; k++) {
        bool in = (k < deg0);
        srcR[k] = in ? ein[st0 + k] : 0;
        wR[k]   = in ? ew[st0 + k] : 0.f;
        if (in && wR[k] != 0.f) am |= (1u << k);
    }
    const int ovfEnd = en0;                       // overflow edges: st0+NREG..en0

    // initial averages (ascending-i order preserved: regs first, then overflow)
    int cur = 0;
    {
        int dg = 0; float s = 0.f;
        #pragma unroll
        for (int k = 0; k < NREG; k++)
            if (am & (1u << k)) { dg++; s += wR[k]; }
        for (int e = st0 + NREG; e < ovfEnd; e++)
            if (alive[e]) { dg++; s += ew[e]; }
        degi[j] = dg;
        favg[0][j] = (dg > 0) ? (s / (float)dg) : 0.f;
    }
    __syncthreads();                             // favg[0] visible to all

    // fixed point: ONE barrier-op per iteration, register-resident edges
    for (;;) {
        const float aj = favg[cur][j];
        int ch = 0;
        #pragma unroll
        for (int k = 0; k < NREG; k++) {
            if (am & (1u << k)) {
                if (!(aj > favg[cur][srcR[k]])) { am &= ~(1u << k); ch = 1; }
            }
        }
        for (int e = st0 + NREG; e < ovfEnd; e++)
            if (alive[e] && !(aj > favg[cur][ein[e]])) { alive[e] = 0; ch = 1; }
        int dg = 0; float s = 0.f;
        #pragma unroll
        for (int k = 0; k < NREG; k++)
            if (am & (1u << k)) { dg++; s += wR[k]; }
        for (int e = st0 + NREG; e < ovfEnd; e++)
            if (alive[e]) { dg++; s += ew[e]; }
        degi[j] = dg;
        favg[cur ^ 1][j] = (dg > 0) ? (s / (float)dg) : 0.f;
        if (!__syncthreads_or(ch)) break;
        cur ^= 1;
    }
    // degi[j] == final alive in-degree

    // compacted offsets over final degrees
    scan288(tid, degi[tid], coffs, wsum);

    // top-144 by in-degree (ties -> smaller index first), int4 reads
    {
        const int dj = degi[j];
        int r = 0;
        const int4* d4 = (const int4*)degi;
        #pragma unroll 4
        for (int q4 = 0; q4 < SSZ / 4; q4++) {
            int4 dd = d4[q4];
            int qb = q4 * 4;
            r += (dd.x > dj) || (dd.x == dj && qb     < j);
            r += (dd.y > dj) || (dd.y == dj && qb + 1 < j);
            r += (dd.z > dj) || (dd.z == dj && qb + 2 < j);
            r += (dd.w > dj) || (dd.w == dj && qb + 3 < j);
        }
        if (r < GSZ) gsel[r] = j;
    }

    // compacted alive edges to global (tk-row-resolved), ascending i
    {
        int ptr = coffs[j];
        #pragma unroll
        for (int k = 0; k < NREG; k++) {
            if (am & (1u << k)) {
                g_ein[b][ptr] = 1 + order[DENS + srcR[k]];
                g_ew[b][ptr]  = wR[k];
                ptr++;
            }
        }
        for (int e = st0 + NREG; e < ovfEnd; e++) {
            if (alive[e]) {
                g_ein[b][ptr] = 1 + order[DENS + ein[e]];
                g_ew[b][ptr]  = ew[e];
                ptr++;
            }
        }
    }
    __syncthreads();

    for (int g = tid; g < GSZ; g += 288) {
        int jj = gsel[g];
        g_selrange[b][g][0] = coffs[jj];
        g_selrange[b][g][1] = coffs[jj] + degi[jj];
    }
    for (int u = tid; u < OUTROWS; u += 288) {
        int row;
        if (u == 0)            row = 0;
        else if (u <= DENS)    row = 1 + order[u - 1];
        else                   row = 1 + order[DENS + gsel[u - 1 - DENS]];
        g_rowmap[b][u] = row;
    }
    for (int v = tid; v < RCOLS; v += 288) {
        int c;
        if (v < DENS) c = order[v];
        else          c = order[DENS + gsel[v - DENS]];
        g_colmap[b][v] = (unsigned short)c;
    }
}

// ---- per-row token computation (shared by both rows of a block) ----------
__device__ __forceinline__ void token_row(const float4* __restrict__ tk4,
                                          float* __restrict__ out,
                                          int b, int u, int row, int t) {
    float4 v = tk4[((size_t)b * NTOK + row) * (DIM / 4) + t];
    if (u > DENS) {                              // aggregated skip-selected row
        const int g  = u - 1 - DENS;
        const int st = g_selrange[b][g][0];
        const int en = g_selrange[b][g][1];
        float4 acc = make_float4(0.f, 0.f, 0.f, 0.f);
        for (int e = st; e < en; e++) {          // alive-only, ascending i
            float w  = g_ew[b][e];
            int   sr = g_ein[b][e];
            float4 sv = tk4[((size_t)b * NTOK + sr) * (DIM / 4) + t];
            acc.x += w * sv.x; acc.y += w * sv.y;
            acc.z += w * sv.z; acc.w += w * sv.w;
        }
        v.x = acc.x + v.x; v.y = acc.y + v.y;
        v.z = acc.z + v.z; v.w = acc.w + v.w;
    }
    __stcs(((float4*)out) + ((size_t)b * OUTROWS + u) * (DIM / 4) + t, v);
}

// -------- fused output kernel: 2 adjacent rows/block, heavy pairs first ----
__global__ __launch_bounds__(192) void k_out(const float* __restrict__ tk,
                                             const float* __restrict__ attn,
                                             float* __restrict__ out) {
    __shared__ float srow[2][PTOK];
    __shared__ unsigned short cmap[RCOLS];
    const int bx = blockIdx.x;                   // 0..216
    const int b  = blockIdx.y;
    const int t  = threadIdx.x;                  // 192 threads
    const int uA = OUTROWS - 1 - 2 * bx;         // 432,430,...,0
    const int uB = uA - 1;                       // 431,...,1,-1 (skip if <0)
    const int rowA = g_rowmap[b][uA];
    const int rowB = (uB >= 0) ? g_rowmap[b][uB] : rowA;

    // stage both attention rows (float4) + shared column map up-front
    const float4* aA = (const float4*)(attn + ((size_t)b * NTOK + rowA) * PTOK);
    const float4* aB = (const float4*)(attn + ((size_t)b * NTOK + rowB) * PTOK);
    if (t < PTOK / 4) {
        ((float4*)srow[0])[t] = aA[t];
        ((float4*)srow[1])[t] = aB[t];
    }
    for (int v2 = t; v2 < RCOLS; v2 += 192) cmap[v2] = g_colmap[b][v2];

    // ---- token rows ----
    const float4* tk4 = (const float4*)tk;
    token_row(tk4, out, b, uA, rowA, t);
    if (uB >= 0) token_row(tk4, out, b, uB, rowB, t);

    // ---- R rows: gather from SMEM, 16B streaming stores ----
    __syncthreads();
    if (t < RCOLS / 4) {
        const int i0 = t * 4;
        const int c0 = cmap[i0], c1 = cmap[i0 + 1], c2 = cmap[i0 + 2], c3 = cmap[i0 + 3];
        float* outR = out + (size_t)BATCH * OUTROWS * DIM;
        float4 r;
        r.x = srow[0][c0]; r.y = srow[0][c1]; r.z = srow[0][c2]; r.w = srow[0][c3];
        __stcs((float4*)(outR + ((size_t)b * OUTROWS + uA) * RCOLS) + t, r);
        if (uB >= 0) {
            r.x = srow[1][c0]; r.y = srow[1][c1]; r.z = srow[1][c2]; r.w = srow[1][c3];
            __stcs((float4*)(outR + ((size_t)b * OUTROWS + uB) * RCOLS) + t, r);
        }
    }
}

// ---------------- launch ---------------------------------------------------
extern "C" void kernel_launch(void* const* d_in, const int* in_sizes, int n_in,
                              void* d_out, int out_size) {
    const float* tk   = (const float*)d_in[0];
    const float* attn = (const float*)d_in[1];
    float* out = (float*)d_out;

    k_order <<<dim3(4, BATCH), 192>>>(attn);
    k_top2  <<<dim3(SSZ / 8, BATCH), 256>>>(attn);
    k_graph2<<<BATCH, 288>>>(attn);
    k_out   <<<dim3((OUTROWS + 1) / 2, BATCH), 192>>>(tk, attn, out);
}